// round 14
// baseline (speedup 1.0000x reference)
#include <cuda_runtime.h>
#include <cstdint>

// Problem constants (D=20, RANK=2 -> o=19 per axis, m=32)
#define O      19
#define DM     20
#define MM     32
#define ROWP   36                    // padded rows for conflict-free LDS.128
#define NT     320                   // 10 warps per CTA; 2 CTAs per SM
#define NWARP  10
#define NITEMS (O*O*2)               // (a,b) x d-half = 722

typedef unsigned long long ull;

// ---- packed f32x2 helpers ----
__device__ __forceinline__ ull f2mul(ull a, ull b) {
    ull r; asm("mul.rn.f32x2 %0, %1, %2;" : "=l"(r) : "l"(a), "l"(b)); return r;
}
__device__ __forceinline__ ull f2fma(ull a, ull b, ull c) {
    ull r; asm("fma.rn.f32x2 %0, %1, %2, %3;" : "=l"(r) : "l"(a), "l"(b), "l"(c)); return r;
}
__device__ __forceinline__ float f2sum(ull v) {
    return __uint_as_float((unsigned)v) + __uint_as_float((unsigned)(v >> 32));
}

// cos table in GLOBAL memory (L1-cached): Ct[n][i][j] = cos(2*pi*n/(32*i+j+2))
__device__ float g_Ct[O * MM * MM];

__global__ void ct_init_kernel() {
    int idx = blockIdx.x * blockDim.x + threadIdx.x;
    if (idx < O * MM * MM) {
        int n = idx >> 10;
        int r = idx & 1023;
        int i = r >> 5, j = r & 31;
        g_Ct[idx] = cosf(6.28318530717958647692f * (float)n / (float)(i * MM + j + 2));
    }
}

// Shared memory layout (floats) — per CTA (63 KB -> 2 CTAs/SM):
//   R   [20][11][32] @ 0     (7040)  (a,b)-pair sums, d-half slice
//   Gab [32][36]     @ 7040  (1152)  P * Ct[A] * Ct[B]
//   Msc [32][36]     @ 8192  (1152)  M_w / 16
//   X   [10][2][10][32] @ 9344 (6400) per-warp private ws/x slots
#define R_OFF    0
#define GAB_OFF  7040
#define MS_OFF   8192
#define X_OFF    9344
#define SMEM_FLOATS 15744
#define SMEM_BYTES (SMEM_FLOATS * 4)   // 62976 B

// ---- cooperative stage: R = 2x2 (a,b) pair-sum slice; Gab = P*Ct[A]*Ct[B] ----
__device__ __forceinline__ void stage_item(const float* __restrict__ H,
                                           const float* __restrict__ Pm,
                                           float* __restrict__ s,
                                           int it, int tid)
{
    const int ab = it >> 1;
    const int dh = it & 1;
    const int A = ab / O;
    const int B = ab % O;
    const int dstart = dh ? 10 : 0;
    const int rows   = dh ? 10 : 11;       // dnum+1

    float* R   = s + R_OFF;
    float* Gab = s + GAB_OFF;

    const int strideB4 = DM * DM * MM / 4;   // 3200 float4
    const int strideA4 = DM * strideB4;
    const float4* H00 = (const float4*)H + (long)A * strideA4 + B * strideB4;
    const float4* H01 = H00 + strideB4;
    const float4* H10 = H00 + strideA4;
    const float4* H11 = H10 + strideB4;
    const int total4 = DM * rows * 8;        // 1600 or 1760
    float4* R4 = (float4*)R;

    #pragma unroll
    for (int base = 0; base < 6; base += 3) {
        int gi[3], si[3];
        bool v[3];
        float4 pa[3], pb[3], ac[3];
        #pragma unroll
        for (int k = 0; k < 3; k++) {
            int e = tid + (base + k) * NT;
            v[k] = (e < total4);
            int c  = e / (rows * 8);
            int rm = e - c * rows * 8;
            int dr = rm >> 3;
            int f  = rm & 7;
            gi[k] = (c * DM + dstart + dr) * 8 + f;
            si[k] = (c * 11 + dr) * 8 + f;
        }
        #pragma unroll
        for (int k = 0; k < 3; k++) if (v[k]) { pa[k] = H00[gi[k]]; pb[k] = H01[gi[k]]; }
        #pragma unroll
        for (int k = 0; k < 3; k++) if (v[k])
            ac[k] = make_float4(pa[k].x + pb[k].x, pa[k].y + pb[k].y,
                                pa[k].z + pb[k].z, pa[k].w + pb[k].w);
        #pragma unroll
        for (int k = 0; k < 3; k++) if (v[k]) { pa[k] = H10[gi[k]]; pb[k] = H11[gi[k]]; }
        #pragma unroll
        for (int k = 0; k < 3; k++) if (v[k])
            R4[si[k]] = make_float4(ac[k].x + pa[k].x + pb[k].x,
                                    ac[k].y + pa[k].y + pb[k].y,
                                    ac[k].z + pa[k].z + pb[k].z,
                                    ac[k].w + pa[k].w + pb[k].w);
    }

    // Gab = P * Ct[A] * Ct[B]  (Ct from global, L1-hot)
    for (int e = tid; e < MM * MM; e += NT) {
        int i = e >> 5, j = e & 31;
        Gab[i * ROWP + j] = Pm[e] * g_Ct[(A * MM + i) * MM + j]
                                  * g_Ct[(B * MM + i) * MM + j];
    }
}

__global__ void __launch_bounds__(NT, 2)
pm4_kernel(const float* __restrict__ H,   // [20,20,20,20,32]
           const float* __restrict__ Mw,  // [32,32]
           const float* __restrict__ P,   // [32,32]
           float* __restrict__ out)       // [19^4, 32]
{
    extern __shared__ float s[];
    float* R   = s + R_OFF;
    float* Gab = s + GAB_OFF;
    float* Msc = s + MS_OFF;

    const int tid  = threadIdx.x;
    const int lane = tid & 31;
    const int w    = tid >> 5;        // warp = c-pair 0..9
    const int c0   = 2 * w;
    const int nc   = (w == 9) ? 1 : 2;
    const int c1   = (nc == 2) ? c0 + 1 : c0;
    const int g    = gridDim.x;

    float* Xw0 = s + X_OFF + w * 640;     // [10 dd][32]
    float* Xw1 = Xw0 + 320;

    // ---- once per CTA: prescaled M ----
    for (int e = tid; e < MM * MM; e += NT) {
        Msc[(e >> 5) * ROWP + (e & 31)] = Mw[e] * 0.0625f;
    }

    // ---- prologue: stage first item ----
    if (blockIdx.x < NITEMS)
        stage_item(H, P, s, blockIdx.x, tid);
    __syncthreads();   // R, Gab, Msc ready

    for (int item = blockIdx.x; item < NITEMS; item += g) {
        const int ab = item >> 1;
        const int dh = item & 1;
        const int dstart = dh ? 10 : 0;
        const int dnum   = dh ? 9 : 10;

        // ---- Phase P-a: this warp's window sums -> private X slots ----
        #pragma unroll 1
        for (int t = 0; t < dnum; t++) {
            const float* r0 = &R[(c0 * 11 + t) * 32 + lane];
            float rA = r0[0]       + r0[32];
            float rB = r0[11 * 32] + r0[12 * 32];
            Xw0[t * 32 + lane] = rA + rB;
            if (nc == 2) {
                float rC = r0[22 * 32] + r0[23 * 32];
                Xw1[t * 32 + lane] = rB + rC;
            }
        }
        __syncwarp();

        // ---- Phase P-b: matvec in place (lane = j; broadcast reads) ----
        {
            ull Mreg[16];
            #pragma unroll
            for (int l4 = 0; l4 < 8; l4++) {
                ulonglong2 m = *reinterpret_cast<const ulonglong2*>(&Msc[lane * ROWP + 4 * l4]);
                Mreg[2 * l4] = m.x; Mreg[2 * l4 + 1] = m.y;
            }
            #pragma unroll 1
            for (int t = 0; t < dnum; t++) {
                ull a0 = 0, a0b = 0, a1 = 0, a1b = 0;
                #pragma unroll
                for (int l4 = 0; l4 < 8; l4++) {
                    ulonglong2 w0 = *reinterpret_cast<const ulonglong2*>(&Xw0[t * 32 + 4 * l4]);
                    a0  = f2fma(Mreg[2 * l4],     w0.x, a0);
                    a0b = f2fma(Mreg[2 * l4 + 1], w0.y, a0b);
                    if (nc == 2) {
                        ulonglong2 w1 = *reinterpret_cast<const ulonglong2*>(&Xw1[t * 32 + 4 * l4]);
                        a1  = f2fma(Mreg[2 * l4],     w1.x, a1);
                        a1b = f2fma(Mreg[2 * l4 + 1], w1.y, a1b);
                    }
                }
                Xw0[t * 32 + lane] = f2sum(a0) + f2sum(a0b);
                if (nc == 2) Xw1[t * 32 + lane] = f2sum(a1) + f2sum(a1b);
            }
        }

        // ---- per-warp G = Gab * Ct[c]  (Gab smem; Ct global L1-hot) ----
        ull G0[16], G1[16];
        {
            const float* cc = &g_Ct[(c0 * MM + lane) * MM];
            const float* cd = &g_Ct[(c1 * MM + lane) * MM];
            #pragma unroll
            for (int l4 = 0; l4 < 8; l4++) {
                ulonglong2 gv = *reinterpret_cast<const ulonglong2*>(&Gab[lane * ROWP + 4 * l4]);
                ulonglong2 cv = *reinterpret_cast<const ulonglong2*>(cc + 4 * l4);
                ulonglong2 dv = *reinterpret_cast<const ulonglong2*>(cd + 4 * l4);
                G0[2 * l4]     = f2mul(gv.x, cv.x);
                G0[2 * l4 + 1] = f2mul(gv.y, cv.y);
                G1[2 * l4]     = f2mul(gv.x, dv.x);
                G1[2 * l4 + 1] = f2mul(gv.y, dv.y);
            }
        }
        __syncwarp();
        __syncthreads();   // all R/Gab reads done; stage below may overwrite

        // ---- Phase C: this warp's windows; cd rows via global LDG (staggered) ----
        {
            const int outBase = ab * (O * O) * MM;
            const int st = w % dnum;
            #pragma unroll 1
            for (int tt = 0; tt < dnum; tt++) {
                int t = st + tt; if (t >= dnum) t -= dnum;
                const int d = dstart + t;
                const float* cdrow = &g_Ct[(d * MM + lane) * MM];
                const float* xv0p  = &Xw0[t * 32];
                const float* xv1p  = &Xw1[t * 32];
                ull A0 = 0, A0b = 0, A1 = 0, A1b = 0;
                #pragma unroll
                for (int l4 = 0; l4 < 8; l4++) {
                    ulonglong2 cd  = *reinterpret_cast<const ulonglong2*>(cdrow + 4 * l4);
                    ulonglong2 xv0 = *reinterpret_cast<const ulonglong2*>(xv0p + 4 * l4);
                    ulonglong2 xv1 = *reinterpret_cast<const ulonglong2*>(xv1p + 4 * l4);
                    A0  = f2fma(f2mul(cd.x, G0[2 * l4]),     xv0.x, A0);
                    A0b = f2fma(f2mul(cd.y, G0[2 * l4 + 1]), xv0.y, A0b);
                    A1  = f2fma(f2mul(cd.x, G1[2 * l4]),     xv1.x, A1);
                    A1b = f2fma(f2mul(cd.y, G1[2 * l4 + 1]), xv1.y, A1b);
                }
                out[outBase + (c0 * O + d) * MM + lane] = f2sum(A0) + f2sum(A0b);
                if (nc == 2)
                    out[outBase + (c1 * O + d) * MM + lane] = f2sum(A1) + f2sum(A1b);
            }
        }

        // ---- tail: stage next item (overlaps other warps' phase C) ----
        if (item + g < NITEMS)
            stage_item(H, P, s, item + g, tid);
        __syncthreads();   // R, Gab ready for next item
    }
}

extern "C" void kernel_launch(void* const* d_in, const int* in_sizes, int n_in,
                              void* d_out, int out_size)
{
    const float* H  = (const float*)d_in[0];
    const float* Mw = (const float*)d_in[1];
    const float* P  = (const float*)d_in[2];
    float* out = (float*)d_out;

    cudaFuncSetAttribute(pm4_kernel, cudaFuncAttributeMaxDynamicSharedMemorySize, SMEM_BYTES);

    int dev = 0, nsm = 148;
    cudaGetDevice(&dev);
    cudaDeviceGetAttribute(&nsm, cudaDevAttrMultiProcessorCount, dev);
    if (nsm <= 0) nsm = 148;

    ct_init_kernel<<<(O * MM * MM + 255) / 256, 256>>>();

    int grid = 2 * nsm;
    if (grid > NITEMS) grid = NITEMS;
    pm4_kernel<<<grid, NT, SMEM_BYTES>>>(H, Mw, P, out);
}

// round 17
// speedup vs baseline: 2.1020x; 2.1020x over previous
#include <cuda_runtime.h>
#include <cstdint>

// Problem constants (D=20, RANK=2 -> o=19 per axis, m=32)
#define O      19
#define DM     20
#define MM     32
#define ROWP   36                    // padded row (floats) -> conflict-free LDS.128
#define CT_STRIDE (MM*ROWP)          // 1152 floats per cos-table slab
#define NT     640                   // 20 warps: (c-pair 0..9) x (d-group 0..1)
#define NWARP  20
#define NITEMS (O*O*2)               // (a,b) x d-half

typedef unsigned long long ull;

// ---- packed f32x2 helpers ----
__device__ __forceinline__ ull f2mul(ull a, ull b) {
    ull r; asm("mul.rn.f32x2 %0, %1, %2;" : "=l"(r) : "l"(a), "l"(b)); return r;
}
__device__ __forceinline__ ull f2fma(ull a, ull b, ull c) {
    ull r; asm("fma.rn.f32x2 %0, %1, %2, %3;" : "=l"(r) : "l"(a), "l"(b), "l"(c)); return r;
}
__device__ __forceinline__ float f2sum(ull v) {
    return __uint_as_float((unsigned)v) + __uint_as_float((unsigned)(v >> 32));
}

// Shared memory layout (floats):
//   Ct  [19][32][36] @ 0      (21888)  Ct[n][i][j] = cos(2*pi*n / (32*i+j+2))
//   R   [20][20][32] @ 21888  (12800)  (a,b)-pair sum of hypervol
//   Gab [32][36]     @ 34688  (1152)   P * Ct[A] * Ct[B]
//   Msc [32][36]     @ 35840  (1152)   M_w / 16 (row-padded)
//   X   [19][10][32] @ 36992  (6080)   x[c, d-dstart, j] for current item
//   WS  [20][2][32]  @ 43072  (1280)   per-warp window-sum staging (2 slots)
#define CT_OFF   0
#define R_OFF    21888
#define GAB_OFF  34688
#define MS_OFF   35840
#define X_OFF    36992
#define WS_OFF   43072
#define SMEM_FLOATS 44352
#define SMEM_BYTES (SMEM_FLOATS * 4)

// ---- R = 2x2 (a,b) pair-sum + Gab build for item `it` (cooperative) ----
__device__ __forceinline__ void stage_item(const float* __restrict__ H,
                                           const float* __restrict__ P,
                                           float* __restrict__ s,
                                           int it, int tid)
{
    const int ab = it >> 1;
    const int A = ab / O;
    const int B = ab % O;
    float* R   = s + R_OFF;
    float* Gab = s + GAB_OFF;
    float* Ct  = s + CT_OFF;

    const int strideB = DM * DM * MM;        // 12800 floats
    const int strideA = DM * strideB;
    const float4* H00 = (const float4*)(H + (long)A * strideA + (long)B * strideB);
    const float4* H01 = H00 + strideB / 4;
    const float4* H10 = H00 + strideA / 4;
    const float4* H11 = H10 + strideB / 4;
    float4* R4 = (float4*)R;

    float4 pa[5], pb[5], acc[5];
    #pragma unroll
    for (int k = 0; k < 5; k++) { pa[k] = H00[tid + k * NT]; pb[k] = H01[tid + k * NT]; }
    #pragma unroll
    for (int k = 0; k < 5; k++) {
        acc[k] = make_float4(pa[k].x + pb[k].x, pa[k].y + pb[k].y,
                             pa[k].z + pb[k].z, pa[k].w + pb[k].w);
    }
    #pragma unroll
    for (int k = 0; k < 5; k++) { pa[k] = H10[tid + k * NT]; pb[k] = H11[tid + k * NT]; }
    #pragma unroll
    for (int k = 0; k < 5; k++) {
        R4[tid + k * NT] = make_float4(acc[k].x + pa[k].x + pb[k].x,
                                       acc[k].y + pa[k].y + pb[k].y,
                                       acc[k].z + pa[k].z + pb[k].z,
                                       acc[k].w + pa[k].w + pb[k].w);
    }

    // Gab = P * Ct[A] * Ct[B] (cooperative; Ct is read-only table)
    for (int e = tid; e < MM * MM; e += NT) {
        int i = e >> 5, j = e & 31;
        Gab[i * ROWP + j] = P[e] * Ct[A * CT_STRIDE + i * ROWP + j]
                                 * Ct[B * CT_STRIDE + i * ROWP + j];
    }
}

__global__ void __launch_bounds__(NT, 1)
pm4_kernel(const float* __restrict__ H,   // [20,20,20,20,32]
           const float* __restrict__ Mw,  // [32,32]
           const float* __restrict__ P,   // [32,32]
           float* __restrict__ out)       // [19^4, 32]
{
    extern __shared__ float s[];
    float* Ct  = s + CT_OFF;
    float* R   = s + R_OFF;
    float* Gab = s + GAB_OFF;
    float* Msc = s + MS_OFF;
    float* WSs = s + WS_OFF;
    float* X   = s + X_OFF;

    const int tid  = threadIdx.x;
    const int lane = tid & 31;
    const int w    = tid >> 5;
    const int cp   = w >> 1;          // 0..9
    const int dg   = w & 1;           // 0..1
    const int c0   = 2 * cp;
    const int nc   = (cp == 9) ? 1 : 2;
    const int c1   = (nc == 2) ? c0 + 1 : c0;
    const int g    = gridDim.x;

    const float TWO_PI = 6.28318530717958647692f;

    // ---- once per CTA: cos table + prescaled M ----
    for (int e = tid; e < O * MM * MM; e += NT) {
        int n = e >> 10;
        int r = e & 1023;
        int i = r >> 5;
        int j = r & 31;
        float per = (float)(i * MM + j + 2);
        Ct[n * CT_STRIDE + i * ROWP + j] = cosf(TWO_PI * (float)n / per);
    }
    for (int e = tid; e < MM * MM; e += NT) {
        Msc[(e >> 5) * ROWP + (e & 31)] = Mw[e] * 0.0625f;
    }
    __syncthreads();   // Ct ready (stage_item reads it)

    // ---- prologue: stage first item ----
    if (blockIdx.x < NITEMS)
        stage_item(H, P, s, blockIdx.x, tid);

    float* ws0 = WSs + w * 64;        // slot 0
    float* ws1 = ws0 + 32;            // slot 1

    for (int item = blockIdx.x; item < NITEMS; item += g) {
        const int ab = item >> 1;
        const int dh = item & 1;
        const int dstart = dh ? 10 : 0;
        const int dnum   = dh ? 9 : 10;

        __syncthreads();   // barrier2: R,Gab ready; X consumed by prev phase C

        // ---- Phase P: window-sums + matvecs, 2 windows per sync round ----
        {
            ull Mreg[16];
            #pragma unroll
            for (int l4 = 0; l4 < 8; l4++) {
                ulonglong2 m = *reinterpret_cast<const ulonglong2*>(&Msc[lane * ROWP + 4 * l4]);
                Mreg[2 * l4] = m.x; Mreg[2 * l4 + 1] = m.y;
            }
            const int npairs = O * dnum;     // (c, dd) windows
            #pragma unroll 1
            for (int p = w; p < npairs; p += 2 * NWARP) {
                const int p2 = p + NWARP;
                const bool has2 = (p2 < npairs);

                // window p
                {
                    const int c  = p / dnum;
                    const int dd = p - c * dnum;
                    const int d  = dstart + dd;
                    const float* r0 = &R[(c * DM + d) * MM + lane];
                    ws0[lane] = (r0[0] + r0[MM]) + (r0[DM * MM] + r0[DM * MM + MM]);
                }
                // window p2 (independent LDS chain)
                if (has2) {
                    const int c  = p2 / dnum;
                    const int dd = p2 - c * dnum;
                    const int d  = dstart + dd;
                    const float* r0 = &R[(c * DM + d) * MM + lane];
                    ws1[lane] = (r0[0] + r0[MM]) + (r0[DM * MM] + r0[DM * MM + MM]);
                }
                __syncwarp();

                // two interleaved matvecs (independent chains)
                ull a0 = 0, a1 = 0, b0 = 0, b1 = 0;
                #pragma unroll
                for (int l4 = 0; l4 < 8; l4++) {
                    ulonglong2 wv0 = *reinterpret_cast<const ulonglong2*>(&ws0[4 * l4]);
                    a0 = f2fma(Mreg[2 * l4],     wv0.x, a0);
                    a1 = f2fma(Mreg[2 * l4 + 1], wv0.y, a1);
                    if (has2) {
                        ulonglong2 wv1 = *reinterpret_cast<const ulonglong2*>(&ws1[4 * l4]);
                        b0 = f2fma(Mreg[2 * l4],     wv1.x, b0);
                        b1 = f2fma(Mreg[2 * l4 + 1], wv1.y, b1);
                    }
                }
                {
                    const int c  = p / dnum;
                    const int dd = p - c * dnum;
                    X[(c * 10 + dd) * 32 + lane] = f2sum(a0) + f2sum(a1);
                }
                if (has2) {
                    const int c  = p2 / dnum;
                    const int dd = p2 - c * dnum;
                    X[(c * 10 + dd) * 32 + lane] = f2sum(b0) + f2sum(b1);
                }
                __syncwarp();
            }
        }

        // ---- per-warp G = Gab * Ct[c] (reads Gab; before barrier3) ----
        ull G0[16], G1[16];
        #pragma unroll
        for (int l4 = 0; l4 < 8; l4++) {
            ulonglong2 gv = *reinterpret_cast<const ulonglong2*>(&Gab[lane * ROWP + 4 * l4]);
            ulonglong2 ca = *reinterpret_cast<const ulonglong2*>(&Ct[c0 * CT_STRIDE + lane * ROWP + 4 * l4]);
            ulonglong2 cb = *reinterpret_cast<const ulonglong2*>(&Ct[c1 * CT_STRIDE + lane * ROWP + 4 * l4]);
            G0[2 * l4]     = f2mul(gv.x, ca.x);
            G0[2 * l4 + 1] = f2mul(gv.y, ca.y);
            G1[2 * l4]     = f2mul(gv.x, cb.x);
            G1[2 * l4 + 1] = f2mul(gv.y, cb.y);
        }
        __syncthreads();   // barrier3: X ready; R,Gab consumed

        // ---- Phase C: warp = (c-pair, d-group), lane = i (staggered dd) ----
        {
            const int outBase = ab * (O * O) * MM;
            const int cnt = (dnum - dg + 1) >> 1;
            int it0 = cp % cnt;
            #pragma unroll 1
            for (int t = 0; t < cnt; t++) {
                int it = it0 + t; if (it >= cnt) it -= cnt;
                const int dd = dg + 2 * it;
                const int d  = dstart + dd;
                const float* cdrow = &Ct[d * CT_STRIDE + lane * ROWP];
                const float* xv0p  = &X[(c0 * 10 + dd) * 32];
                const float* xv1p  = &X[(c1 * 10 + dd) * 32];
                ull A0 = 0, A0b = 0, A1 = 0, A1b = 0;
                #pragma unroll
                for (int l4 = 0; l4 < 8; l4++) {
                    ulonglong2 cd  = *reinterpret_cast<const ulonglong2*>(cdrow + 4 * l4);
                    ulonglong2 xv0 = *reinterpret_cast<const ulonglong2*>(xv0p + 4 * l4);
                    ulonglong2 xv1 = *reinterpret_cast<const ulonglong2*>(xv1p + 4 * l4);
                    A0  = f2fma(f2mul(cd.x, G0[2 * l4]),     xv0.x, A0);
                    A0b = f2fma(f2mul(cd.y, G0[2 * l4 + 1]), xv0.y, A0b);
                    A1  = f2fma(f2mul(cd.x, G1[2 * l4]),     xv1.x, A1);
                    A1b = f2fma(f2mul(cd.y, G1[2 * l4 + 1]), xv1.y, A1b);
                }
                out[outBase + (c0 * O + d) * MM + lane] = f2sum(A0) + f2sum(A0b);
                if (nc == 2)
                    out[outBase + (c1 * O + d) * MM + lane] = f2sum(A1) + f2sum(A1b);
            }
        }

        // ---- tail: stage next item (R + Gab) — overlaps other warps' phase C ----
        if (item + g < NITEMS)
            stage_item(H, P, s, item + g, tid);
    }
}

extern "C" void kernel_launch(void* const* d_in, const int* in_sizes, int n_in,
                              void* d_out, int out_size)
{
    const float* H  = (const float*)d_in[0];
    const float* Mw = (const float*)d_in[1];
    const float* P  = (const float*)d_in[2];
    float* out = (float*)d_out;

    cudaFuncSetAttribute(pm4_kernel, cudaFuncAttributeMaxDynamicSharedMemorySize, SMEM_BYTES);

    int dev = 0, nsm = 148;
    cudaGetDevice(&dev);
    cudaDeviceGetAttribute(&nsm, cudaDevAttrMultiProcessorCount, dev);
    if (nsm <= 0) nsm = 148;
    int grid = nsm > NITEMS ? NITEMS : nsm;

    pm4_kernel<<<grid, NT, SMEM_BYTES>>>(H, Mw, P, out);
}